// round 2
// baseline (speedup 1.0000x reference)
#include <cuda_runtime.h>
#include <cuda_bf16.h>
#include <cstdint>

// Problem constants (fixed shapes)
#define BATCH  64
#define TSTEPS 2048
#define M_ROWS (BATCH * TSTEPS)   // 131072
#define HID    64
#define G4     256                // 4*H gates

// ---------------------------------------------------------------------------
// Scratch (static __device__ arrays; no allocation allowed)
// ---------------------------------------------------------------------------
__device__ float    g_xg1[(size_t)M_ROWS * G4];   // layer1 input-gate preacts
__device__ float    g_xg2[(size_t)M_ROWS * G4];   // layer2 input-gate preacts
__device__ uint32_t g_xph[(size_t)M_ROWS * 64];   // x packed bf16x2 (hi)
__device__ uint32_t g_xpl[(size_t)M_ROWS * 64];   // x packed bf16x2 (lo residual)
__device__ uint32_t g_h1h[(size_t)M_ROWS * 32];   // h1*mask1 packed bf16x2 (hi)
__device__ uint32_t g_h1l[(size_t)M_ROWS * 32];   // h1*mask1 packed bf16x2 (lo)
__device__ uint4    g_wf1[32 * 8 * 32];           // W_ih1 fragment-ordered (hi+lo)
__device__ uint4    g_wf2[32 * 4 * 32];           // W_ih2 fragment-ordered (hi+lo)

// ---------------------------------------------------------------------------
// Helpers
// ---------------------------------------------------------------------------
__device__ __forceinline__ uint32_t packbf(float lo, float hi) {
    // elem0 (low 16 bits) = lo, elem1 = hi
    uint32_t r;
    asm("cvt.rn.bf16x2.f32 %0, %1, %2;" : "=r"(r) : "f"(hi), "f"(lo));
    return r;
}
__device__ __forceinline__ unsigned long long pack64(float lo, float hi) {
    unsigned long long r;
    asm("mov.b64 %0, {%1, %2};" : "=l"(r) : "f"(lo), "f"(hi));
    return r;
}
__device__ __forceinline__ void unpack64(unsigned long long v, float& lo, float& hi) {
    asm("mov.b64 {%0, %1}, %2;" : "=f"(lo), "=f"(hi) : "l"(v));
}
__device__ __forceinline__ void fma2(unsigned long long& acc, unsigned long long a,
                                     unsigned long long b) {
    asm("fma.rn.f32x2 %0, %1, %2, %0;" : "+l"(acc) : "l"(a), "l"(b));
}
__device__ __forceinline__ float bf16_round(float f) {
    return __bfloat162float(__float2bfloat16_rn(f));
}
__device__ __forceinline__ float sig_f(float x) {
    return __fdividef(1.0f, 1.0f + __expf(-x));
}
__device__ __forceinline__ float tanh_f(float x) {
    return __fdividef(2.0f, 1.0f + __expf(-2.0f * x)) - 1.0f;
}
__device__ __forceinline__ void mma16816(float* c, const uint32_t* a,
                                         uint32_t b0, uint32_t b1) {
    asm("mma.sync.aligned.m16n8k16.row.col.f32.bf16.bf16.f32 "
        "{%0,%1,%2,%3}, {%4,%5,%6,%7}, {%8,%9}, {%0,%1,%2,%3};"
        : "+f"(c[0]), "+f"(c[1]), "+f"(c[2]), "+f"(c[3])
        : "r"(a[0]), "r"(a[1]), "r"(a[2]), "r"(a[3]), "r"(b0), "r"(b1));
}

// ---------------------------------------------------------------------------
// Prep: split x (fp32) into hi/lo bf16x2 packed pairs  [row][pair]
// ---------------------------------------------------------------------------
__global__ void prep_x_kernel(const float* __restrict__ x) {
    int i = blockIdx.x * blockDim.x + threadIdx.x;   // over M_ROWS*64 pairs
    if (i >= M_ROWS * 64) return;
    float2 f = ((const float2*)x)[i];
    float hx = bf16_round(f.x), hy = bf16_round(f.y);
    g_xph[i] = packbf(f.x, f.y);
    g_xpl[i] = packbf(f.x - hx, f.y - hy);
}

// ---------------------------------------------------------------------------
// Prep: W_ih -> mma-fragment-ordered hi/lo bf16, one uint4 per (ntile,kiter,lane)
// uint4 = { b0_hi, b1_hi, b0_lo, b1_lo }
// ---------------------------------------------------------------------------
__global__ void prep_w_kernel(const float* __restrict__ W, int K, int which) {
    int KI = K / 16;
    int total = 32 * KI * 32;
    int i = blockIdx.x * blockDim.x + threadIdx.x;
    if (i >= total) return;
    int lane = i & 31;
    int ki   = (i >> 5) % KI;
    int nt   = i / (32 * KI);
    int tig = lane & 3, gid = lane >> 2;
    int n  = nt * 8 + gid;
    int k0 = ki * 16 + tig * 2;
    const float* Wn = W + (size_t)n * K;
    float w00 = Wn[k0],     w01 = Wn[k0 + 1];
    float w10 = Wn[k0 + 8], w11 = Wn[k0 + 9];
    uint32_t b0h = packbf(w00, w01);
    uint32_t b1h = packbf(w10, w11);
    uint32_t b0l = packbf(w00 - bf16_round(w00), w01 - bf16_round(w01));
    uint32_t b1l = packbf(w10 - bf16_round(w10), w11 - bf16_round(w11));
    uint4 v; v.x = b0h; v.y = b1h; v.z = b0l; v.w = b1l;
    if (which == 1) g_wf1[(nt * KI + ki) * 32 + lane] = v;
    else            g_wf2[(nt * KI + ki) * 32 + lane] = v;
}

// ---------------------------------------------------------------------------
// GEMM: out[M,256] = A[M,K] @ W[256,K]^T + (b_ih + b_hh)
// 3-term bf16 split (Ah*Bh + Ah*Bl + Al*Bh) for ~fp32 accuracy.
// Block: 256 threads (8 warps). Warp tile: m32 x n64. Block tile: m128 x n128.
// Grid: (M/128, 2).
// ---------------------------------------------------------------------------
template<int KI, int LAYER>
__global__ __launch_bounds__(256, 1) void gemm_kernel(
    const float* __restrict__ bias_a, const float* __restrict__ bias_b)
{
    const int PPR = KI * 8;  // packed pairs per row
    const uint32_t* __restrict__ Ah = (LAYER == 1) ? g_xph : g_h1h;
    const uint32_t* __restrict__ Al = (LAYER == 1) ? g_xpl : g_h1l;
    const uint4*    __restrict__ WF = (LAYER == 1) ? g_wf1 : g_wf2;
    float*          __restrict__ out = (LAYER == 1) ? g_xg1 : g_xg2;

    int tid = threadIdx.x;
    int lane = tid & 31, wid = tid >> 5;
    int tig = lane & 3, gid = lane >> 2;
    int wm = wid & 3, wn = wid >> 2;
    int rb = blockIdx.x * 128 + wm * 32;          // warp m base (2 tiles of 16)
    int ntBase = (blockIdx.y * 2 + wn) * 8;       // 8 n-tiles of 8

    float acc[2][8][4];
#pragma unroll
    for (int mt = 0; mt < 2; mt++)
#pragma unroll
        for (int j = 0; j < 8; j++)
#pragma unroll
            for (int q = 0; q < 4; q++) acc[mt][j][q] = 0.0f;

#pragma unroll
    for (int ki = 0; ki < KI; ki++) {
        uint32_t a[2][4], al[2][4];
#pragma unroll
        for (int mt = 0; mt < 2; mt++) {
            size_t r0 = (size_t)(rb + mt * 16 + gid) * PPR + ki * 8;
            a[mt][0]  = __ldg(Ah + r0 + tig);
            a[mt][1]  = __ldg(Ah + r0 + 8 * PPR + tig);
            a[mt][2]  = __ldg(Ah + r0 + 4 + tig);
            a[mt][3]  = __ldg(Ah + r0 + 8 * PPR + 4 + tig);
            al[mt][0] = __ldg(Al + r0 + tig);
            al[mt][1] = __ldg(Al + r0 + 8 * PPR + tig);
            al[mt][2] = __ldg(Al + r0 + 4 + tig);
            al[mt][3] = __ldg(Al + r0 + 8 * PPR + 4 + tig);
        }
#pragma unroll
        for (int j = 0; j < 8; j++) {
            uint4 bf = __ldg(&WF[((ntBase + j) * KI + ki) * 32 + lane]);
#pragma unroll
            for (int mt = 0; mt < 2; mt++) {
                mma16816(acc[mt][j], a[mt],  bf.x, bf.y);  // Ah * Bh
                mma16816(acc[mt][j], a[mt],  bf.z, bf.w);  // Ah * Bl
                mma16816(acc[mt][j], al[mt], bf.x, bf.y);  // Al * Bh
            }
        }
    }

    // epilogue: add biases, store float2 pairs
#pragma unroll
    for (int j = 0; j < 8; j++) {
        int nc = (ntBase + j) * 8 + tig * 2;
        float bs0 = __ldg(bias_a + nc) + __ldg(bias_b + nc);
        float bs1 = __ldg(bias_a + nc + 1) + __ldg(bias_b + nc + 1);
#pragma unroll
        for (int mt = 0; mt < 2; mt++) {
            size_t r0 = (size_t)(rb + mt * 16 + gid);
            float2 v0 = make_float2(acc[mt][j][0] + bs0, acc[mt][j][1] + bs1);
            float2 v1 = make_float2(acc[mt][j][2] + bs0, acc[mt][j][3] + bs1);
            *(float2*)(out + r0 * G4 + nc)       = v0;
            *(float2*)(out + (r0 + 8) * G4 + nc) = v1;
        }
    }
}

// ---------------------------------------------------------------------------
// LSTM recurrence. 1 block per batch element, 128 threads.
// Thread p owns gate pair (2p, 2p+1): 64 packed f32x2 FMAs against register-
// resident W_hh columns; h kept duplicated ({h,h}) in SMEM for direct LDS.64
// as the packed multiplier. fp32 throughout.
// LAYER==1: emits (h*mask) as hi/lo bf16x2 packed pairs for GEMM2.
// LAYER==2: emits relu(h*mask) fp32 to d_out.
// ---------------------------------------------------------------------------
template<int LAYER>
__global__ __launch_bounds__(128, 1) void rec_kernel(
    const float* __restrict__ Whh,   // [256,64]
    const float* __restrict__ mask,  // [B,64]
    float* __restrict__ out)         // LAYER==2 only
{
    const float* __restrict__ xg = (LAYER == 1) ? g_xg1 : g_xg2;
    int b = blockIdx.x;
    int p = threadIdx.x;             // 0..127 -> gates 2p, 2p+1

    // Preload packed weight columns: wv[k] = {Whh[2p][k], Whh[2p+1][k]}
    unsigned long long wv[64];
#pragma unroll
    for (int k = 0; k < 64; k++)
        wv[k] = pack64(__ldg(Whh + (size_t)(2 * p) * 64 + k),
                       __ldg(Whh + (size_t)(2 * p + 1) * 64 + k));

    __shared__ unsigned long long hq[64];  // duplicated h: {h_j, h_j}
    __shared__ float2 act2[128];           // staged activations (256 gates)
    float* act = (float*)act2;

    if (p < 64) hq[p] = 0ull;
    float c = 0.0f;
    float mval = (p < 64) ? __ldg(mask + b * 64 + p) : 0.0f;

    const float* xgb = xg + (size_t)b * TSTEPS * G4 + 2 * p;
    float2 xc = *(const float2*)(xgb);
    float2 xn = *(const float2*)(xgb + G4);
    __syncthreads();

    for (int t = 0; t < TSTEPS; t++) {
        // prefetch xg pair for t+2 (distance 2 to cover L2/DRAM latency)
        float2 xf = make_float2(0.0f, 0.0f);
        if (t + 2 < TSTEPS) xf = __ldg((const float2*)(xgb + (size_t)(t + 2) * G4));

        // gate-pair dot product: 64 packed FMAs, 4 accumulators
        unsigned long long a0 = 0ull, a1 = 0ull, a2 = 0ull, a3 = 0ull;
#pragma unroll
        for (int k = 0; k < 64; k += 4) {
            fma2(a0, hq[k],     wv[k]);
            fma2(a1, hq[k + 1], wv[k + 1]);
            fma2(a2, hq[k + 2], wv[k + 2]);
            fma2(a3, hq[k + 3], wv[k + 3]);
        }
        float g0, g1, s0, s1, u0, u1;
        unpack64(a0, g0, g1); unpack64(a1, s0, s1);
        g0 += s0; g1 += s1;
        unpack64(a2, s0, s1); unpack64(a3, u0, u1);
        s0 += u0; s1 += u1;
        g0 += s0 + xc.x;
        g1 += s1 + xc.y;

        float A0, A1;
        if (p >= 64 && p < 96) {   // gates [128,192) = 'g' gate -> tanh
            A0 = tanh_f(g0); A1 = tanh_f(g1);
        } else {                   // i, f, o -> sigmoid
            A0 = sig_f(g0);  A1 = sig_f(g1);
        }
        act2[p] = make_float2(A0, A1);
        __syncthreads();

        if (p < 64) {
            float iv = act[p], fv = act[64 + p], gv = act[128 + p], ov = act[192 + p];
            c = fv * c + iv * gv;
            float hval = ov * tanh_f(c);
            hq[p] = pack64(hval, hval);
            float hm = hval * mval;
            if (LAYER == 1) {
                float hb = hm - bf16_round(hm);                 // lo residual
                float hmN = __shfl_down_sync(0xffffffffu, hm, 1);
                float hbN = __shfl_down_sync(0xffffffffu, hb, 1);
                if ((p & 1) == 0) {
                    size_t row = (size_t)b * TSTEPS + t;
                    g_h1h[row * 32 + (p >> 1)] = packbf(hm, hmN);
                    g_h1l[row * 32 + (p >> 1)] = packbf(hb, hbN);
                }
            } else {
                out[((size_t)b * TSTEPS + t) * HID + p] = fmaxf(hm, 0.0f);
            }
        }
        xc = xn; xn = xf;
        __syncthreads();
    }
}

// ---------------------------------------------------------------------------
// Launch
// ---------------------------------------------------------------------------
extern "C" void kernel_launch(void* const* d_in, const int* in_sizes, int n_in,
                              void* d_out, int out_size) {
    const float* x     = (const float*)d_in[0];
    const float* W_ih1 = (const float*)d_in[1];
    const float* W_hh1 = (const float*)d_in[2];
    const float* b_ih1 = (const float*)d_in[3];
    const float* b_hh1 = (const float*)d_in[4];
    const float* W_ih2 = (const float*)d_in[5];
    const float* W_hh2 = (const float*)d_in[6];
    const float* b_ih2 = (const float*)d_in[7];
    const float* b_hh2 = (const float*)d_in[8];
    const float* mask1 = (const float*)d_in[9];
    const float* mask2 = (const float*)d_in[10];
    float* out = (float*)d_out;

    // split x into hi/lo bf16 pairs
    prep_x_kernel<<<(M_ROWS * 64) / 256, 256>>>(x);
    // fragment-order the input weight matrices (hi/lo)
    prep_w_kernel<<<(32 * 8 * 32 + 127) / 128, 128>>>(W_ih1, 128, 1);
    prep_w_kernel<<<(32 * 4 * 32 + 127) / 128, 128>>>(W_ih2, 64, 2);

    // layer 1: input GEMM then recurrence
    gemm_kernel<8, 1><<<dim3(M_ROWS / 128, 2), 256>>>(b_ih1, b_hh1);
    rec_kernel<1><<<BATCH, 128>>>(W_hh1, mask1, nullptr);

    // layer 2: input GEMM (on h1*mask1) then recurrence + relu
    gemm_kernel<4, 2><<<dim3(M_ROWS / 128, 2), 256>>>(b_ih2, b_hh2);
    rec_kernel<2><<<BATCH, 128>>>(W_hh2, mask2, out);
}

// round 3
// speedup vs baseline: 1.5396x; 1.5396x over previous
#include <cuda_runtime.h>
#include <cuda_bf16.h>
#include <cstdint>

#define BATCH  64
#define TSTEPS 2048
#define M_ROWS (BATCH * TSTEPS)   // 131072
#define HID    64
#define G4     256

typedef unsigned long long ull;

// ---------------------------------------------------------------------------
// Scratch (static __device__ arrays; no allocation allowed)
// ---------------------------------------------------------------------------
__device__ float    g_xg1[(size_t)M_ROWS * G4];   // layer1 gate preacts, PAIR layout
__device__ float    g_xg2[(size_t)M_ROWS * G4];   // layer2 gate preacts, PAIR layout
__device__ uint32_t g_xph[(size_t)M_ROWS * 64];   // x packed bf16x2 (hi)
__device__ uint32_t g_xpl[(size_t)M_ROWS * 64];   // x packed bf16x2 (lo residual)
__device__ uint4    g_wf1[32 * 8 * 32];           // W_ih1 fragment-ordered (hi+lo)
__device__ unsigned g_flag[BATCH];                // producer progress (rows ready)

// Pair layout for xg: 128 ull per row; slot s<64 holds {i_s, f_s}; slot 64+s holds {g_s, o_s}.

// ---------------------------------------------------------------------------
// Helpers
// ---------------------------------------------------------------------------
__device__ __forceinline__ uint32_t packbf(float lo, float hi) {
    uint32_t r;
    asm("cvt.rn.bf16x2.f32 %0, %1, %2;" : "=r"(r) : "f"(hi), "f"(lo));
    return r;
}
__device__ __forceinline__ ull pack64(float lo, float hi) {
    ull r; asm("mov.b64 %0, {%1, %2};" : "=l"(r) : "f"(lo), "f"(hi)); return r;
}
__device__ __forceinline__ void unpack64(ull v, float& lo, float& hi) {
    asm("mov.b64 {%0, %1}, %2;" : "=f"(lo), "=f"(hi) : "l"(v));
}
__device__ __forceinline__ void fma2(ull& acc, ull a, ull b) {
    asm("fma.rn.f32x2 %0, %1, %2, %0;" : "+l"(acc) : "l"(a), "l"(b));
}
__device__ __forceinline__ ull add2(ull a, ull b) {
    ull r; asm("add.rn.f32x2 %0, %1, %2;" : "=l"(r) : "l"(a), "l"(b)); return r;
}
__device__ __forceinline__ float bf16_round(float f) {
    return __bfloat162float(__float2bfloat16_rn(f));
}
__device__ __forceinline__ float sig_f(float x) {
    return __fdividef(1.0f, 1.0f + __expf(-x));
}
__device__ __forceinline__ float tanh_f(float x) {
    return __fdividef(2.0f, 1.0f + __expf(-2.0f * x)) - 1.0f;
}
__device__ __forceinline__ void mma16816(float* c, const uint32_t* a,
                                         uint32_t b0, uint32_t b1) {
    asm("mma.sync.aligned.m16n8k16.row.col.f32.bf16.bf16.f32 "
        "{%0,%1,%2,%3}, {%4,%5,%6,%7}, {%8,%9}, {%0,%1,%2,%3};"
        : "+f"(c[0]), "+f"(c[1]), "+f"(c[2]), "+f"(c[3])
        : "r"(a[0]), "r"(a[1]), "r"(a[2]), "r"(a[3]), "r"(b0), "r"(b1));
}
__device__ __forceinline__ unsigned ld_acq(const unsigned* p) {
    unsigned v;
    asm volatile("ld.acquire.gpu.global.u32 %0, [%1];" : "=r"(v) : "l"(p) : "memory");
    return v;
}
__device__ __forceinline__ void st_rel(unsigned* p, unsigned v) {
    asm volatile("st.release.gpu.global.u32 [%0], %1;" :: "l"(p), "r"(v) : "memory");
}

// 64-long packed dot product: sum_k hp[k]*wv[k], hp in smem (broadcast), wv in regs
__device__ __forceinline__ ull dot64(const ull* hp, const ull* wv) {
    ull a0 = 0ull, a1 = 0ull, a2 = 0ull, a3 = 0ull;
#pragma unroll
    for (int k = 0; k < 64; k += 4) {
        fma2(a0, hp[k],     wv[k]);
        fma2(a1, hp[k + 1], wv[k + 1]);
        fma2(a2, hp[k + 2], wv[k + 2]);
        fma2(a3, hp[k + 3], wv[k + 3]);
    }
    return add2(add2(a0, a1), add2(a2, a3));
}

// ---------------------------------------------------------------------------
// Prep: split x into hi/lo bf16x2 packed pairs; also reset progress flags
// ---------------------------------------------------------------------------
__global__ void prep_x_kernel(const float* __restrict__ x) {
    int i = blockIdx.x * blockDim.x + threadIdx.x;
    if (i < BATCH) g_flag[i] = 0;
    if (i >= M_ROWS * 64) return;
    float2 f = ((const float2*)x)[i];
    float hx = bf16_round(f.x), hy = bf16_round(f.y);
    g_xph[i] = packbf(f.x, f.y);
    g_xpl[i] = packbf(f.x - hx, f.y - hy);
}

// Prep W_ih1 -> mma-fragment-ordered hi/lo bf16
__global__ void prep_w_kernel(const float* __restrict__ W) {
    const int KI = 8, K = 128;
    int total = 32 * KI * 32;
    int i = blockIdx.x * blockDim.x + threadIdx.x;
    if (i >= total) return;
    int lane = i & 31;
    int ki   = (i >> 5) % KI;
    int nt   = i / (32 * KI);
    int tig = lane & 3, gid = lane >> 2;
    int n  = nt * 8 + gid;
    int k0 = ki * 16 + tig * 2;
    const float* Wn = W + (size_t)n * K;
    float w00 = Wn[k0],     w01 = Wn[k0 + 1];
    float w10 = Wn[k0 + 8], w11 = Wn[k0 + 9];
    uint4 v;
    v.x = packbf(w00, w01);
    v.y = packbf(w10, w11);
    v.z = packbf(w00 - bf16_round(w00), w01 - bf16_round(w01));
    v.w = packbf(w10 - bf16_round(w10), w11 - bf16_round(w11));
    g_wf1[(nt * KI + ki) * 32 + lane] = v;
}

// ---------------------------------------------------------------------------
// GEMM1: g_xg1 = x @ W_ih1^T + (b_ih1+b_hh1), 3-term bf16 split, pair-layout out.
// Block 256 thr (8 warps), warp tile m16 x n64, block m64 x n128, grid (2048, 2).
// ---------------------------------------------------------------------------
__device__ __forceinline__ void st_pair(float* base, size_t r, int c, float v) {
    int slot = (c & 63) + ((c & 128) ? 64 : 0);
    int e    = (c >> 6) & 1;
    base[r * G4 + slot * 2 + e] = v;
}

__global__ __launch_bounds__(256, 2) void gemm_kernel(
    const float* __restrict__ bias_a, const float* __restrict__ bias_b)
{
    const int KI = 8, PPR = 64;
    int tid = threadIdx.x;
    int lane = tid & 31, wid = tid >> 5;
    int tig = lane & 3, gid = lane >> 2;
    int wm = wid & 3, wn = wid >> 2;
    int rb = blockIdx.x * 64 + wm * 16;
    int ntBase = (blockIdx.y * 2 + wn) * 8;

    float acc[8][4];
#pragma unroll
    for (int j = 0; j < 8; j++)
#pragma unroll
        for (int q = 0; q < 4; q++) acc[j][q] = 0.0f;

#pragma unroll
    for (int ki = 0; ki < KI; ki++) {
        uint32_t a[4], al[4];
        size_t r0 = (size_t)(rb + gid) * PPR + ki * 8;
        a[0]  = __ldg(g_xph + r0 + tig);
        a[1]  = __ldg(g_xph + r0 + 8 * PPR + tig);
        a[2]  = __ldg(g_xph + r0 + 4 + tig);
        a[3]  = __ldg(g_xph + r0 + 8 * PPR + 4 + tig);
        al[0] = __ldg(g_xpl + r0 + tig);
        al[1] = __ldg(g_xpl + r0 + 8 * PPR + tig);
        al[2] = __ldg(g_xpl + r0 + 4 + tig);
        al[3] = __ldg(g_xpl + r0 + 8 * PPR + 4 + tig);
#pragma unroll
        for (int j = 0; j < 8; j++) {
            uint4 bf = __ldg(&g_wf1[((ntBase + j) * KI + ki) * 32 + lane]);
            mma16816(acc[j], a,  bf.x, bf.y);   // Ah * Bh
            mma16816(acc[j], a,  bf.z, bf.w);   // Ah * Bl
            mma16816(acc[j], al, bf.x, bf.y);   // Al * Bh
        }
    }

#pragma unroll
    for (int j = 0; j < 8; j++) {
        int nc = (ntBase + j) * 8 + tig * 2;
        float bs0 = __ldg(bias_a + nc) + __ldg(bias_b + nc);
        float bs1 = __ldg(bias_a + nc + 1) + __ldg(bias_b + nc + 1);
        size_t r = (size_t)(rb + gid);
        st_pair(g_xg1, r,     nc,     acc[j][0] + bs0);
        st_pair(g_xg1, r,     nc + 1, acc[j][1] + bs1);
        st_pair(g_xg1, r + 8, nc,     acc[j][2] + bs0);
        st_pair(g_xg1, r + 8, nc + 1, acc[j][3] + bs1);
    }
}

// ---------------------------------------------------------------------------
// Fused pipelined recurrence.
// Grid = 128 CTAs x 256 threads.
//  CTA b in [0,64):  PRODUCER for sequence b.
//    warps 0-3 (tid<128): layer1 recurrence. Warp w owns h[16w..16w+16);
//      lanes<16 compute packed {i,f}, lanes>=16 packed {g,o}; gates exchanged
//      via shfl_xor(16); double-buffered hq -> ONE __syncthreads per step.
//    warps 4-7: fp32 GEMV xg2(t-1) = W_ih2 @ h1m(t-1) + bias, one step behind,
//      sharing the same barrier; publishes g_flag[b] (rows ready) every 16 steps.
//  CTA 64+b: CONSUMER: layer2 recurrence on g_xg2, gated by ld.acquire on
//    g_flag[b]; writes relu(h*mask2) to out.
// ---------------------------------------------------------------------------
__global__ __launch_bounds__(256, 1) void fused_rec_kernel(
    const float* __restrict__ Whh1, const float* __restrict__ mask1,
    const float* __restrict__ Wih2, const float* __restrict__ bih2,
    const float* __restrict__ bhh2,
    const float* __restrict__ Whh2, const float* __restrict__ mask2,
    float* __restrict__ out)
{
    __shared__ ull hq[2][64];   // duplicated h: {h,h}
    __shared__ ull hqm[2][64];  // duplicated h*mask (producer only)

    int tid  = threadIdx.x;
    int bid  = blockIdx.x;
    bool producer = bid < BATCH;
    int b = producer ? bid : bid - BATCH;

    if (producer) {
        if (tid < 128) {
            // ---- layer1 recurrence warps ----
            int lane = tid & 31, w = tid >> 5;
            int jj = (w << 4) + (lane & 15);
            bool isIF = lane < 16;
            int rA = isIF ? jj : 128 + jj;
            ull wv[64];
#pragma unroll
            for (int k = 0; k < 64; k++)
                wv[k] = pack64(__ldg(Whh1 + (size_t)rA * 64 + k),
                               __ldg(Whh1 + (size_t)(rA + 64) * 64 + k));
            float mval = __ldg(mask1 + b * 64 + jj);
            if (tid < 64) {
                hq[0][tid] = 0ull; hq[1][tid] = 0ull;
                hqm[0][tid] = 0ull; hqm[1][tid] = 0ull;
            }
            float c = 0.0f;
            const ull* xgb = (const ull*)g_xg1 + (size_t)b * TSTEPS * 128
                             + (isIF ? jj : 64 + jj);
            __syncthreads();                               // bar0
            ull xc = __ldg(xgb), xn = __ldg(xgb + 128);
            for (int t = 0; t < TSTEPS; t++) {
                int p = t & 1;
                ull xf = 0ull;
                if (t + 2 < TSTEPS) xf = __ldg(xgb + (size_t)(t + 2) * 128);
                ull s = add2(dot64(hq[p], wv), xc);
                float gA, gB; unpack64(s, gA, gB);
                float A0, A1;
                if (isIF) { A0 = sig_f(gA);  A1 = sig_f(gB); }
                else      { A0 = tanh_f(gA); A1 = sig_f(gB); }
                float sg = __shfl_xor_sync(0xffffffffu, A0, 16);
                float so = __shfl_xor_sync(0xffffffffu, A1, 16);
                if (isIF) {
                    c = A1 * c + A0 * sg;
                    float h = so * tanh_f(c);
                    hq[p ^ 1][jj] = pack64(h, h);
                    float hm = h * mval;
                    hqm[p ^ 1][jj] = pack64(hm, hm);
                }
                xc = xn; xn = xf;
                __syncthreads();                           // 1 bar per step
            }
            __syncthreads();                               // post (match gemv)
        } else {
            // ---- GEMV warps: xg2 row t-1 each iteration ----
            int s = tid - 128;                             // pair slot 0..127
            int rA = (s < 64) ? s : 128 + (s - 64);
            ull wxv[64];
#pragma unroll
            for (int k = 0; k < 64; k++)
                wxv[k] = pack64(__ldg(Wih2 + (size_t)rA * 64 + k),
                                __ldg(Wih2 + (size_t)(rA + 64) * 64 + k));
            ull bias = pack64(__ldg(bih2 + rA) + __ldg(bhh2 + rA),
                              __ldg(bih2 + rA + 64) + __ldg(bhh2 + rA + 64));
            ull* dst = (ull*)g_xg2 + (size_t)b * TSTEPS * 128 + s;
            __syncthreads();                               // bar0
            for (int t = 0; t < TSTEPS; t++) {
                int p = t & 1;
                if (t > 0) {
                    ull sum = add2(dot64(hqm[p], wxv), bias);
                    dst[(size_t)(t - 1) * 128] = sum;
                }
                if (tid == 128 && t > 0 && (t & 15) == 0) {
                    __threadfence();
                    st_rel(&g_flag[b], (unsigned)(t - 1)); // rows 0..t-2 ready
                }
                __syncthreads();
            }
            // final row T-1: hm(T-1) sits in hqm[T & 1]
            {
                ull sum = add2(dot64(hqm[TSTEPS & 1], wxv), bias);
                dst[(size_t)(TSTEPS - 1) * 128] = sum;
            }
            __syncthreads();                               // post
            if (tid == 128) {
                __threadfence();
                st_rel(&g_flag[b], (unsigned)TSTEPS);
            }
        }
    } else {
        // =================== CONSUMER: layer2 ===================
        if (tid < 128) {
            int lane = tid & 31, w = tid >> 5;
            int jj = (w << 4) + (lane & 15);
            bool isIF = lane < 16;
            int rA = isIF ? jj : 128 + jj;
            ull wv[64];
#pragma unroll
            for (int k = 0; k < 64; k++)
                wv[k] = pack64(__ldg(Whh2 + (size_t)rA * 64 + k),
                               __ldg(Whh2 + (size_t)(rA + 64) * 64 + k));
            float mval = __ldg(mask2 + b * 64 + jj);
            if (tid < 64) { hq[0][tid] = 0ull; hq[1][tid] = 0ull; }
            float c = 0.0f;
            const ull* xgb = (const ull*)g_xg2 + (size_t)b * TSTEPS * 128
                             + (isIF ? jj : 64 + jj);
            unsigned avail = 0;
            __syncthreads();                               // bar0
            while (avail < 2u) { avail = ld_acq(&g_flag[b]); if (avail < 2u) __nanosleep(64); }
            ull xc = xgb[0], xn = xgb[128];
            for (int t = 0; t < TSTEPS; t++) {
                int p = t & 1;
                ull xf = 0ull;
                if (t + 2 < TSTEPS) {
                    unsigned need = (unsigned)(t + 3);
                    while (avail < need) { avail = ld_acq(&g_flag[b]); if (avail < need) __nanosleep(64); }
                    xf = xgb[(size_t)(t + 2) * 128];
                }
                ull s = add2(dot64(hq[p], wv), xc);
                float gA, gB; unpack64(s, gA, gB);
                float A0, A1;
                if (isIF) { A0 = sig_f(gA);  A1 = sig_f(gB); }
                else      { A0 = tanh_f(gA); A1 = sig_f(gB); }
                float sg = __shfl_xor_sync(0xffffffffu, A0, 16);
                float so = __shfl_xor_sync(0xffffffffu, A1, 16);
                if (isIF) {
                    c = A1 * c + A0 * sg;
                    float h = so * tanh_f(c);
                    hq[p ^ 1][jj] = pack64(h, h);
                    out[((size_t)b * TSTEPS + t) * HID + jj] = fmaxf(h * mval, 0.0f);
                }
                xc = xn; xn = xf;
                __syncthreads();
            }
        } else {
            // barrier-matching loop
            __syncthreads();                               // bar0
            for (int t = 0; t < TSTEPS; t++) __syncthreads();
        }
    }
}

// ---------------------------------------------------------------------------
// Launch
// ---------------------------------------------------------------------------
extern "C" void kernel_launch(void* const* d_in, const int* in_sizes, int n_in,
                              void* d_out, int out_size) {
    const float* x     = (const float*)d_in[0];
    const float* W_ih1 = (const float*)d_in[1];
    const float* W_hh1 = (const float*)d_in[2];
    const float* b_ih1 = (const float*)d_in[3];
    const float* b_hh1 = (const float*)d_in[4];
    const float* W_ih2 = (const float*)d_in[5];
    const float* W_hh2 = (const float*)d_in[6];
    const float* b_ih2 = (const float*)d_in[7];
    const float* b_hh2 = (const float*)d_in[8];
    const float* mask1 = (const float*)d_in[9];
    const float* mask2 = (const float*)d_in[10];
    float* out = (float*)d_out;

    prep_x_kernel<<<(M_ROWS * 64) / 256, 256>>>(x);
    prep_w_kernel<<<(32 * 8 * 32 + 127) / 128, 128>>>(W_ih1);

    // layer1 input GEMM (tensor cores, pair-layout epilogue)
    gemm_kernel<<<dim3(M_ROWS / 64, 2), 256>>>(b_ih1, b_hh1);

    // fused pipelined recurrence: layer1 rec + layer2 input GEMV + layer2 rec
    fused_rec_kernel<<<2 * BATCH, 256>>>(W_hh1, mask1, W_ih2, b_ih2, b_hh2,
                                         W_hh2, mask2, out);
}